// round 7
// baseline (speedup 1.0000x reference)
#include <cuda_runtime.h>
#include <cstdint>

// Problem constants
#define HID   1024
#define INP   128
#define NBAT  32
#define LSTEP 2048
#define KTOT  1152            // 1024 (h) + 128 (x)
#define COLS  64              // hidden columns per CTA (lane covers 2)
#define ROWSB 4               // batch rows per CTA
#define NCOLB 16              // column blocks
#define NBATB 8               // batch groups
#define GRID  (NCOLB * NBATB) // 128 CTAs (single wave)
#define NTHR  512
#define NWARP 16
#define KW    (KTOT / NWARP)  // 72 k per warp
#define NCH   (KW / 4)        // 18 chunks of 4 k
#define NWF   (KW / 2)        // 36 f32x2 W registers (column 0)

// Per-GROUP accumulating barrier flag. Each CTA RED-adds 1 per step; pollers
// wait for base + NCOLB*t. Monotonic across launches/replays (wrap-safe cmp).
__device__ unsigned g_flag[NBATB];

// Packed dual fp32 FMA (sm_100+)
__device__ __forceinline__ unsigned long long fma2(unsigned long long a,
                                                   unsigned long long b,
                                                   unsigned long long c) {
    unsigned long long d;
    asm("fma.rn.f32x2 %0, %1, %2, %3;" : "=l"(d) : "l"(a), "l"(b), "l"(c));
    return d;
}

__device__ __forceinline__ unsigned long long pack2(float x, float y) {
    unsigned long long r;
    asm("mov.b64 %0, {%1, %2};" : "=l"(r) : "f"(x), "f"(y));
    return r;
}

__device__ __forceinline__ float unpack_sum(unsigned long long v) {
    float lo, hi;
    asm("mov.b64 {%0, %1}, %2;" : "=f"(lo), "=f"(hi) : "l"(v));
    return lo + hi;
}

// smem layout (floats):
//   Ws    [288][32][4]     : 36864  (W for col1 = j0+32+lane; [w*NCH+ch][lane][4k])
//   part  [ROWSB][COLS][17]:  4352  (pad 17 -> conflict-free)
//   bias_s[COLS]           :    64
#define SM_WS  0
#define SM_P   (288 * 32 * 4)
#define PSTR   17
#define SM_B   (SM_P + ROWSB * COLS * PSTR)
#define SM_TOT (SM_B + COLS)            // 41280 floats = 165120 bytes

__global__ void __launch_bounds__(NTHR, 1)
reservoir_persistent(const float* __restrict__ input,   // (L, N, I)
                     const float* __restrict__ h_init,  // (N, H)
                     const float* __restrict__ W_in,    // (H, I)
                     const float* __restrict__ bias,    // (H)
                     const float* __restrict__ W_h,     // (H, H)
                     float* __restrict__ out)           // (L, N, H)
{
    extern __shared__ float smem[];
    float* Ws     = smem + SM_WS;
    float* part_s = smem + SM_P;
    float* bias_s = smem + SM_B;

    const int tid = threadIdx.x;
    const int bx  = blockIdx.x;
    const int c   = bx & (NCOLB - 1);   // column block id (0..15)
    const int g   = bx >> 4;            // batch group id (0..7)
    const int j0  = c * COLS;
    const int n0  = g * ROWSB;

    // Epoch base (tid0 only; prior launch fully drained before we start)
    unsigned bar_base = 0;
    if (tid == 0) bar_base = *(volatile unsigned*)&g_flag[g];

    const int w    = tid >> 5;          // warp id = K-slice (72 k)
    const int lane = tid & 31;
    const int k0   = w * KW;
    const int col0 = j0 + lane;         // W in registers
    // col1 = j0 + 32 + lane            // W in shared

    // ---- One-time: W for col0 into registers (f32x2 packed; boundaries even) ----
    unsigned long long w0[NWF];
    #pragma unroll
    for (int i = 0; i < NWF; ++i) {
        int k = k0 + 2 * i;
        float2 v;
        if (k < HID) v = *(const float2*)(W_h + (size_t)col0 * HID + k);
        else         v = *(const float2*)(W_in + (size_t)col0 * INP + (k - HID));
        w0[i] = pack2(v.x, v.y);
    }
    // ---- One-time: W for col1 into shared: Ws[cg][l][kk] ----
    for (int i = tid; i < 288 * 32 * 4; i += NTHR) {
        int kk = i & 3;
        int l  = (i >> 2) & 31;
        int cg = i >> 7;
        int k  = 4 * cg + kk;
        int cl = j0 + 32 + l;
        float v = (k < HID) ? W_h[(size_t)cl * HID + k]
                            : W_in[(size_t)cl * INP + (k - HID)];
        Ws[i] = v;
    }
    if (tid < COLS) bias_s[tid] = bias[j0 + tid];
    __syncthreads();

    // Reduction indices (first 256 threads)
    const int rn = tid >> 6;       // 0..3
    const int rj = tid & 63;       // 0..63

    const ulonglong2* wsp = (const ulonglong2*)Ws + (size_t)(w * NCH) * 32 + lane;

    volatile unsigned* flagp = (volatile unsigned*)&g_flag[g];

    for (int t = 0; t < LSTEP; ++t) {
        // ---- Wait for step t-1 of our batch group (tid0 polls, bar fans out) ----
        if (t > 0) {
            if (tid == 0) {
                const unsigned target = bar_base + (unsigned)(NCOLB * t);
                unsigned v = *flagp;
                while ((int)(v - target) < 0) v = *flagp;
                __threadfence();   // acquire
            }
            __syncthreads();
        }

        // ---- Compute: h/x read DIRECTLY from L2 (.cg 16B broadcasts) ----
        const float* hbase = (t == 0) ? (h_init + (size_t)n0 * HID)
                                      : (out + ((size_t)(t - 1) * NBAT + n0) * HID);
        const float* xbase = input + ((size_t)t * NBAT + n0) * INP;

        // Per-row byte pointers at this warp's k origin (x origin may be
        // "negative"; only dereferenced for chunks with k >= HID).
        const char* hr[ROWSB];
        const char* xr[ROWSB];
        #pragma unroll
        for (int r = 0; r < ROWSB; ++r) {
            hr[r] = (const char*)(hbase + (size_t)r * HID) + (size_t)k0 * 4;
            xr[r] = (const char*)(xbase + (size_t)r * INP) + ((long)k0 - HID) * 4;
        }

        unsigned long long acc[2 * ROWSB];   // [2r]=col0, [2r+1]=col1
        #pragma unroll
        for (int i = 0; i < 2 * ROWSB; ++i) acc[i] = 0ull;

        #pragma unroll
        for (int ch = 0; ch < NCH; ++ch) {
            const bool is_h = (k0 + 4 * ch) < HID;   // uniform per warp-chunk
            ulonglong2 wv = wsp[ch * 32];            // col1 W, conflict-free
            #pragma unroll
            for (int r = 0; r < ROWSB; ++r) {
                const ulonglong2* ap =
                    (const ulonglong2*)((is_h ? hr[r] : xr[r]) + 16 * ch);
                ulonglong2 a = __ldcg(ap);           // L2 broadcast, L1-bypass
                acc[2 * r]     = fma2(a.x, w0[2 * ch],     acc[2 * r]);
                acc[2 * r]     = fma2(a.y, w0[2 * ch + 1], acc[2 * r]);
                acc[2 * r + 1] = fma2(a.x, wv.x,           acc[2 * r + 1]);
                acc[2 * r + 1] = fma2(a.y, wv.y,           acc[2 * r + 1]);
            }
        }

        // ---- Dump partials: part[r][col][w], stride-17 conflict-free ----
        #pragma unroll
        for (int r = 0; r < ROWSB; ++r) {
            part_s[(r * COLS + lane) * PSTR + w]      = unpack_sum(acc[2 * r]);
            part_s[(r * COLS + 32 + lane) * PSTR + w] = unpack_sum(acc[2 * r + 1]);
        }
        __syncthreads();

        // ---- Reduce 16 partials + bias + tanh + store h(t) ----
        if (tid < 256) {
            float s = bias_s[rj];
            #pragma unroll
            for (int ww = 0; ww < NWARP; ++ww)
                s += part_s[(rn * COLS + rj) * PSTR + ww];
            float hv = tanhf(s);
            out[((size_t)t * NBAT + n0 + rn) * HID + j0 + rj] = hv;
        }
        __syncthreads();

        // ---- Arrive: leaderless RED accumulate (release) ----
        if (tid == 0) {
            __threadfence();                 // h(t) visible at L2 before flag
            atomicAdd((unsigned*)&g_flag[g], 1u);   // result unused -> RED
        }
    }
}

extern "C" void kernel_launch(void* const* d_in, const int* in_sizes, int n_in,
                              void* d_out, int out_size) {
    (void)in_sizes; (void)n_in; (void)out_size;
    const float* input  = (const float*)d_in[0];  // (2048, 32, 128)
    const float* h_init = (const float*)d_in[1];  // (32, 1024)
    const float* W_in   = (const float*)d_in[2];  // (1024, 128)
    const float* bias   = (const float*)d_in[3];  // (1024)
    const float* W_h    = (const float*)d_in[4];  // (1024, 1024)
    float* out = (float*)d_out;                   // (2048, 32, 1024)

    cudaFuncSetAttribute(reservoir_persistent,
                         cudaFuncAttributeMaxDynamicSharedMemorySize,
                         SM_TOT * (int)sizeof(float));
    reservoir_persistent<<<GRID, NTHR, SM_TOT * sizeof(float)>>>(
        input, h_init, W_in, bias, W_h, out);
}